// round 16
// baseline (speedup 1.0000x reference)
#include <cuda_runtime.h>
#include <cuda_fp16.h>
#include <cstdint>

#define N_NODES   100000
#define NUM_E     1600000
#define DIM_IN    64
#define HDIM      128
#define NLAYERS   3
#define NGRAPHS   512
#define NCLASSES  6
#define LN_EPS    1e-5f
#define NBLK      98
#define NTILES    782          // ceil(100000/128)
#define CNT_PROJ  NLAYERS
#define NCNT      (NLAYERS + 1)

// layer smem (half2 units): weights [128kp][136] + A tile [128][68]
#define SWH_STRIDE 136
#define SWH_ELEMS  (128 * SWH_STRIDE)
#define SAT_STRIDE 68
#define SAT_ELEMS  (128 * SAT_STRIDE)
#define LAYER_SMEM ((SWH_ELEMS + SAT_ELEMS) * 4)

// ---------------- scratch ----------------
__device__ __half2 g_hf[(size_t)N_NODES * HDIM / 2];     // ping
__device__ __half2 g_haux[(size_t)N_NODES * HDIM / 2];   // pong
__device__ float   g_invdeg[N_NODES];
__device__ int     g_deg[N_NODES];
__device__ int     g_off[N_NODES + 1];
__device__ int     g_cursor[N_NODES];
__device__ int     g_csr[NUM_E];
__device__ int     g_bsum[NBLK];
__device__ int     g_boff[NBLK];
__device__ int     g_cnt[NCNT];
__device__ float   g_gate[N_NODES];

// ---------------- helpers ----------------
__device__ __forceinline__ void mma_f16(float& d0, float& d1, float& d2, float& d3,
                                        unsigned a0, unsigned a1, unsigned a2, unsigned a3,
                                        unsigned b0, unsigned b1) {
    asm volatile("mma.sync.aligned.m16n8k16.row.col.f32.f16.f16.f32 "
                 "{%0,%1,%2,%3},{%4,%5,%6,%7},{%8,%9},{%0,%1,%2,%3};"
                 : "+f"(d0), "+f"(d1), "+f"(d2), "+f"(d3)
                 : "r"(a0), "r"(a1), "r"(a2), "r"(a3), "r"(b0), "r"(b1));
}
__device__ __forceinline__ unsigned h2u(__half2 h) { return *(unsigned*)&h; }
__device__ __forceinline__ __half2 u2h(unsigned u) { return *(__half2*)&u; }
__device__ __forceinline__ float elu_fast(float n) {
    return n > 0.f ? n : (__expf(n) - 1.0f);
}
__device__ __forceinline__ void cp8(void* smem_dst, const void* gsrc, bool pred) {
    unsigned sa = (unsigned)__cvta_generic_to_shared(smem_dst);
    int sz = pred ? 8 : 0;
    asm volatile("cp.async.ca.shared.global [%0], [%1], 8, %2;" :: "r"(sa), "l"(gsrc), "r"(sz));
}
#define CP_COMMIT() asm volatile("cp.async.commit_group;")
#define CP_WAIT0()  asm volatile("cp.async.wait_group 0;")

// ---------------- init / degree / CSR ----------------
__global__ void init_kernel() {
    int i = blockIdx.x * blockDim.x + threadIdx.x;
    int stride = gridDim.x * blockDim.x;
    for (int idx = i; idx < N_NODES; idx += stride) g_deg[idx] = 0;
    if (i < NCNT) g_cnt[i] = 0;
}
__global__ void deg_kernel(const int* __restrict__ ei) {
    int i = blockIdx.x * blockDim.x + threadIdx.x;
    int stride = gridDim.x * blockDim.x;
    for (int e = i; e < NUM_E; e += stride) atomicAdd(&g_deg[ei[NUM_E + e]], 1);
}
__global__ void __launch_bounds__(1024) scan_a_kernel() {
    int i = blockIdx.x * 1024 + threadIdx.x;
    int lane = threadIdx.x & 31;
    int v = (i < N_NODES) ? g_deg[i] : 0;
#pragma unroll
    for (int o = 16; o; o >>= 1) v += __shfl_xor_sync(0xffffffffu, v, o);
    __shared__ int wsum[32];
    if (lane == 0) wsum[threadIdx.x >> 5] = v;
    __syncthreads();
    if (threadIdx.x < 32) {
        int t = wsum[threadIdx.x];
#pragma unroll
        for (int o = 16; o; o >>= 1) t += __shfl_xor_sync(0xffffffffu, t, o);
        if (threadIdx.x == 0) g_bsum[blockIdx.x] = t;
    }
}
__global__ void __launch_bounds__(128) scan_b_kernel() {
    __shared__ int sm[128];
    int t = threadIdx.x;
    int v = (t < NBLK) ? g_bsum[t] : 0;
    sm[t] = v; __syncthreads();
    for (int o = 1; o < 128; o <<= 1) {
        int tmp = (t >= o) ? sm[t - o] : 0;
        __syncthreads();
        sm[t] += tmp;
        __syncthreads();
    }
    if (t < NBLK) g_boff[t] = sm[t] - v;
    if (t == NBLK - 1) g_off[N_NODES] = sm[t];
}
__global__ void __launch_bounds__(1024) scan_c_kernel() {
    __shared__ int sm[1024];
    int t = threadIdx.x;
    int i = blockIdx.x * 1024 + t;
    int v = (i < N_NODES) ? g_deg[i] : 0;
    sm[t] = v; __syncthreads();
    for (int o = 1; o < 1024; o <<= 1) {
        int tmp = (t >= o) ? sm[t - o] : 0;
        __syncthreads();
        sm[t] += tmp;
        __syncthreads();
    }
    if (i < N_NODES) {
        int off = g_boff[blockIdx.x] + sm[t] - v;
        g_off[i] = off;
        g_cursor[i] = off;
        g_invdeg[i] = 1.0f / fmaxf((float)v, 1.0f);
    }
}
__global__ void fill_kernel(const int* __restrict__ ei) {
    int i = blockIdx.x * blockDim.x + threadIdx.x;
    int stride = gridDim.x * blockDim.x;
    for (int e = i; e < NUM_E; e += stride) {
        int src = ei[e];
        int dst = ei[NUM_E + e];
        int p = atomicAdd(&g_cursor[dst], 1);
        g_csr[p] = src;
    }
}

// ---------------- projection (fp16 mma, staged A): hf = relu(x @ W + b) ----------------
__global__ void __launch_bounds__(256) proj_kernel(const float* __restrict__ x,
                                                   const float* __restrict__ w,
                                                   const float* __restrict__ b) {
    __shared__ __half2 sW[32 * 136];
    __shared__ __half2 sX[128 * 36];
    __shared__ float sbias[128];
    __shared__ int s_tile;
    int tid = threadIdx.x, lane = tid & 31, warp = tid >> 5;
    int tg = lane & 3, g = lane >> 2;
    for (int i = tid; i < 32 * 128; i += 256) {
        int kp = i >> 7, n = i & 127;
        sW[kp * 136 + n] = __floats2half2_rn(w[(2 * kp) * HDIM + n], w[(2 * kp + 1) * HDIM + n]);
    }
    if (tid < 128) sbias[tid] = b[tid];
    __syncthreads();

    while (true) {
        if (tid == 0) s_tile = atomicAdd(&g_cnt[CNT_PROJ], 1);
        __syncthreads();
        int tile = s_tile;
        if (tile >= NTILES) break;
        int rowbase = tile * 128;

        for (int f = tid; f < 2048; f += 256) {
            int r = f >> 4, q = f & 15;
            int grow = rowbase + r;
            float4 v = make_float4(0.f, 0.f, 0.f, 0.f);
            if (grow < N_NODES) v = ((const float4*)(x + (size_t)grow * DIM_IN))[q];
            sX[r * 36 + q * 2]     = __floats2half2_rn(v.x, v.y);
            sX[r * 36 + q * 2 + 1] = __floats2half2_rn(v.z, v.w);
        }
        __syncthreads();

        float acc[16][4];
#pragma unroll
        for (int t = 0; t < 16; t++) { acc[t][0]=0.f; acc[t][1]=0.f; acc[t][2]=0.f; acc[t][3]=0.f; }

        const __half2* a0p = &sX[(warp * 16 + g) * 36];
        const __half2* a1p = a0p + 8 * 36;
#pragma unroll
        for (int s = 0; s < 4; s++) {
            int kpo = s * 8;
            unsigned A0 = h2u(a0p[kpo + tg]);
            unsigned A1 = h2u(a1p[kpo + tg]);
            unsigned A2 = h2u(a0p[kpo + tg + 4]);
            unsigned A3 = h2u(a1p[kpo + tg + 4]);
            const __half2* bb  = &sW[(kpo + tg) * 136 + g];
            const __half2* bb2 = bb + 4 * 136;
#pragma unroll
            for (int t = 0; t < 16; t++)
                mma_f16(acc[t][0], acc[t][1], acc[t][2], acc[t][3],
                        A0, A1, A2, A3, h2u(bb[t * 8]), h2u(bb2[t * 8]));
        }

        int grow0 = rowbase + warp * 16 + g;
        int grow1 = grow0 + 8;
        if (grow0 < N_NODES) {
#pragma unroll
            for (int t = 0; t < 16; t++) {
                int c = t * 8 + tg * 2;
                g_hf[((size_t)grow0 * HDIM + c) >> 1] =
                    __floats2half2_rn(fmaxf(acc[t][0] + sbias[c], 0.f),
                                      fmaxf(acc[t][1] + sbias[c + 1], 0.f));
            }
        }
        if (grow1 < N_NODES) {
#pragma unroll
            for (int t = 0; t < 16; t++) {
                int c = t * 8 + tg * 2;
                g_hf[((size_t)grow1 * HDIM + c) >> 1] =
                    __floats2half2_rn(fmaxf(acc[t][2] + sbias[c], 0.f),
                                      fmaxf(acc[t][3] + sbias[c + 1], 0.f));
            }
        }
        __syncthreads();
    }
}

// ---------------- fused layer: gather + GEMM(K=256) + LN + ELU + residual ----------------
// 2 CTAs/SM (104.5KB smem). hin/hout ping-pong. Gather writes the aggr tile
// straight into smem (phase 1 A operand); h tile then overwrites it (phase 2
// A operand + residual). No g_aggr round trip.
__global__ void __launch_bounds__(256, 2) layer_kernel(const float* __restrict__ wl,
                                                       const float* __restrict__ bl,
                                                       const float* __restrict__ wr,
                                                       const float* __restrict__ lg,
                                                       const float* __restrict__ lb,
                                                       int lidx) {
    extern __shared__ __half2 smh[];
    __half2* sW = smh;                 // [128 kp][136]
    __half2* sA = smh + SWH_ELEMS;     // [128 rows][68]
    __shared__ float sGB[384];
    __shared__ int s_tile;
    int tid = threadIdx.x, lane = tid & 31, warp = tid >> 5;
    int half = lane >> 4, lh = lane & 15;
    int tg = lane & 3, g = lane >> 2;

    const __half2* hin  = (lidx & 1) ? g_haux : g_hf;
    __half2*       hout = (lidx & 1) ? g_hf   : g_haux;
    const uint4* hb4 = reinterpret_cast<const uint4*>(hin);

    if (tid < 128) { sGB[tid] = lg[tid]; sGB[128 + tid] = lb[tid]; sGB[256 + tid] = bl[tid]; }
    for (int i = tid; i < 128 * 128; i += 256) {
        int kp = i >> 7, n = i & 127;
        float w0, w1;
        if (kp < 64) { w0 = wl[(2 * kp) * HDIM + n];       w1 = wl[(2 * kp + 1) * HDIM + n]; }
        else { int r = 2 * kp - 128; w0 = wr[r * HDIM + n]; w1 = wr[(r + 1) * HDIM + n]; }
        sW[kp * SWH_STRIDE + n] = __floats2half2_rn(w0, w1);
    }
    __syncthreads();

    while (true) {
        if (tid == 0) s_tile = atomicAdd(&g_cnt[lidx], 1);
        __syncthreads();
        int tile = s_tile;
        if (tile >= NTILES) break;
        int rowbase = tile * 128;

        // ---- phase G: CSR mean-gather into sA (warp handles 16 nodes) ----
#define FOLD(U) { float2 f; \
    f = __half22float2(u2h((U).x)); a0 += f.x; a1 += f.y; \
    f = __half22float2(u2h((U).y)); a2 += f.x; a3 += f.y; \
    f = __half22float2(u2h((U).z)); a4 += f.x; a5 += f.y; \
    f = __half22float2(u2h((U).w)); a6 += f.x; a7 += f.y; }
        for (int i = 0; i < 16; i++) {
            int arow = warp * 16 + i;
            int node = rowbase + arow;
            float a0=0.f,a1=0.f,a2=0.f,a3=0.f,a4=0.f,a5=0.f,a6=0.f,a7=0.f;
            float inv = 1.0f;
            if (node < N_NODES) {
                int beg = g_off[node], end = g_off[node + 1];
                int cnt = end - beg;
                int e16 = beg + (cnt & ~15);
                int e = beg + half;
                for (; e < e16; e += 16) {
                    int i0 = g_csr[e],      i1 = g_csr[e + 2];
                    int i2 = g_csr[e + 4],  i3 = g_csr[e + 6];
                    int i4 = g_csr[e + 8],  i5 = g_csr[e + 10];
                    int i6 = g_csr[e + 12], i7 = g_csr[e + 14];
                    uint4 u0 = hb4[(size_t)i0 * 16 + lh];
                    uint4 u1 = hb4[(size_t)i1 * 16 + lh];
                    uint4 u2 = hb4[(size_t)i2 * 16 + lh];
                    uint4 u3 = hb4[(size_t)i3 * 16 + lh];
                    uint4 u4 = hb4[(size_t)i4 * 16 + lh];
                    uint4 u5 = hb4[(size_t)i5 * 16 + lh];
                    uint4 u6 = hb4[(size_t)i6 * 16 + lh];
                    uint4 u7 = hb4[(size_t)i7 * 16 + lh];
                    uint4 s;
                    s.x = h2u(__hadd2(__hadd2(__hadd2(u2h(u0.x), u2h(u1.x)), __hadd2(u2h(u2.x), u2h(u3.x))),
                                      __hadd2(__hadd2(u2h(u4.x), u2h(u5.x)), __hadd2(u2h(u6.x), u2h(u7.x)))));
                    s.y = h2u(__hadd2(__hadd2(__hadd2(u2h(u0.y), u2h(u1.y)), __hadd2(u2h(u2.y), u2h(u3.y))),
                                      __hadd2(__hadd2(u2h(u4.y), u2h(u5.y)), __hadd2(u2h(u6.y), u2h(u7.y)))));
                    s.z = h2u(__hadd2(__hadd2(__hadd2(u2h(u0.z), u2h(u1.z)), __hadd2(u2h(u2.z), u2h(u3.z))),
                                      __hadd2(__hadd2(u2h(u4.z), u2h(u5.z)), __hadd2(u2h(u6.z), u2h(u7.z)))));
                    s.w = h2u(__hadd2(__hadd2(__hadd2(u2h(u0.w), u2h(u1.w)), __hadd2(u2h(u2.w), u2h(u3.w))),
                                      __hadd2(__hadd2(u2h(u4.w), u2h(u5.w)), __hadd2(u2h(u6.w), u2h(u7.w)))));
                    FOLD(s)
                }
                int end_even = end - (cnt & 1);
                for (; e < end_even; e += 2) {
                    uint4 u = hb4[(size_t)g_csr[e] * 16 + lh];
                    FOLD(u)
                }
                if ((cnt & 1) && half == 0) {
                    uint4 u = hb4[(size_t)g_csr[end - 1] * 16 + lh];
                    FOLD(u)
                }
                inv = g_invdeg[node];
            }
            a0 += __shfl_xor_sync(0xffffffffu, a0, 16);
            a1 += __shfl_xor_sync(0xffffffffu, a1, 16);
            a2 += __shfl_xor_sync(0xffffffffu, a2, 16);
            a3 += __shfl_xor_sync(0xffffffffu, a3, 16);
            a4 += __shfl_xor_sync(0xffffffffu, a4, 16);
            a5 += __shfl_xor_sync(0xffffffffu, a5, 16);
            a6 += __shfl_xor_sync(0xffffffffu, a6, 16);
            a7 += __shfl_xor_sync(0xffffffffu, a7, 16);
            if (half == 0) {
                uint4 o;
                o.x = h2u(__floats2half2_rn(a0 * inv, a1 * inv));
                o.y = h2u(__floats2half2_rn(a2 * inv, a3 * inv));
                o.z = h2u(__floats2half2_rn(a4 * inv, a5 * inv));
                o.w = h2u(__floats2half2_rn(a6 * inv, a7 * inv));
                *(uint4*)&sA[arow * SAT_STRIDE + lh * 4] = o;
            }
        }
#undef FOLD
        __syncthreads();

        float acc[16][4];
#pragma unroll
        for (int t = 0; t < 16; t++) { acc[t][0]=0.f; acc[t][1]=0.f; acc[t][2]=0.f; acc[t][3]=0.f; }

        // ---- phase 1: mma over K=0..127 (aggr tile) ----
        {
            const __half2* a0p = &sA[(warp * 16 + g) * SAT_STRIDE];
            const __half2* a1p = a0p + 8 * SAT_STRIDE;
#pragma unroll
            for (int s2 = 0; s2 < 8; s2++) {
                int kpo = s2 * 8;
                unsigned A0 = h2u(a0p[kpo + tg]);
                unsigned A1 = h2u(a1p[kpo + tg]);
                unsigned A2 = h2u(a0p[kpo + tg + 4]);
                unsigned A3 = h2u(a1p[kpo + tg + 4]);
                const __half2* bb  = &sW[(kpo + tg) * SWH_STRIDE + g];
                const __half2* bb2 = bb + 4 * SWH_STRIDE;
#pragma unroll
                for (int t = 0; t < 16; t++)
                    mma_f16(acc[t][0], acc[t][1], acc[t][2], acc[t][3],
                            A0, A1, A2, A3, h2u(bb[t * 8]), h2u(bb2[t * 8]));
            }
        }
        __syncthreads();

        // ---- phase 1.5: load h tile (coalesced cp.async) into sA ----
        for (int f = tid; f < 4096; f += 256) {   // 128 rows x 32 uint2
            int r = f >> 5, j = f & 31;
            int grow = rowbase + r;
            bool ok = grow < N_NODES;
            int growc = ok ? grow : (N_NODES - 1);
            const void* src = (const void*)(((const uint2*)(hin + (size_t)growc * 64)) + j);
            cp8(&sA[r * SAT_STRIDE + j * 2], src, ok);
        }
        CP_COMMIT();
        CP_WAIT0();
        __syncthreads();

        // ---- phase 2: mma over K=128..255 (h tile) ----
        {
            const __half2* a0p = &sA[(warp * 16 + g) * SAT_STRIDE];
            const __half2* a1p = a0p + 8 * SAT_STRIDE;
#pragma unroll
            for (int s2 = 0; s2 < 8; s2++) {
                int kpo = s2 * 8;
                unsigned A0 = h2u(a0p[kpo + tg]);
                unsigned A1 = h2u(a1p[kpo + tg]);
                unsigned A2 = h2u(a0p[kpo + tg + 4]);
                unsigned A3 = h2u(a1p[kpo + tg + 4]);
                const __half2* bb  = &sW[(64 + kpo + tg) * SWH_STRIDE + g];
                const __half2* bb2 = bb + 4 * SWH_STRIDE;
#pragma unroll
                for (int t = 0; t < 16; t++)
                    mma_f16(acc[t][0], acc[t][1], acc[t][2], acc[t][3],
                            A0, A1, A2, A3, h2u(bb[t * 8]), h2u(bb2[t * 8]));
            }
        }

        // ---- epilogue: bias, LN, ELU, residual (residual from sA h tile) ----
        int grow0 = rowbase + warp * 16 + g;
        int grow1 = grow0 + 8;
        bool v0 = grow0 < N_NODES, v1 = grow1 < N_NODES;
        float s0 = 0.f, q0 = 0.f, s1 = 0.f, q1 = 0.f;
#pragma unroll
        for (int t = 0; t < 16; t++) {
            int c = t * 8 + tg * 2;
            float bb0 = sGB[256 + c], bb1 = sGB[256 + c + 1];
            acc[t][0] += bb0; acc[t][1] += bb1; acc[t][2] += bb0; acc[t][3] += bb1;
            s0 += acc[t][0] + acc[t][1]; q0 += acc[t][0]*acc[t][0] + acc[t][1]*acc[t][1];
            s1 += acc[t][2] + acc[t][3]; q1 += acc[t][2]*acc[t][2] + acc[t][3]*acc[t][3];
        }
#pragma unroll
        for (int o = 1; o <= 2; o <<= 1) {
            s0 += __shfl_xor_sync(0xffffffffu, s0, o);
            q0 += __shfl_xor_sync(0xffffffffu, q0, o);
            s1 += __shfl_xor_sync(0xffffffffu, s1, o);
            q1 += __shfl_xor_sync(0xffffffffu, q1, o);
        }
        float mu0 = s0 * (1.0f / HDIM), mu1 = s1 * (1.0f / HDIM);
        float rs0 = rsqrtf(q0 * (1.0f / HDIM) - mu0 * mu0 + LN_EPS);
        float rs1 = rsqrtf(q1 * (1.0f / HDIM) - mu1 * mu1 + LN_EPS);
        int arow0 = warp * 16 + g;
        if (v0) {
#pragma unroll
            for (int t = 0; t < 16; t++) {
                int c = t * 8 + tg * 2;
                float n0 = (acc[t][0] - mu0) * rs0 * sGB[c] + sGB[128 + c];
                float n1 = (acc[t][1] - mu0) * rs0 * sGB[c + 1] + sGB[128 + c + 1];
                float2 r = __half22float2(sA[arow0 * SAT_STRIDE + (c >> 1)]);
                hout[((size_t)grow0 * HDIM + c) >> 1] =
                    __floats2half2_rn(elu_fast(n0) + r.x, elu_fast(n1) + r.y);
            }
        }
        if (v1) {
#pragma unroll
            for (int t = 0; t < 16; t++) {
                int c = t * 8 + tg * 2;
                float n0 = (acc[t][2] - mu1) * rs1 * sGB[c] + sGB[128 + c];
                float n1 = (acc[t][3] - mu1) * rs1 * sGB[c + 1] + sGB[128 + c + 1];
                float2 r = __half22float2(sA[(arow0 + 8) * SAT_STRIDE + (c >> 1)]);
                hout[((size_t)grow1 * HDIM + c) >> 1] =
                    __floats2half2_rn(elu_fast(n0) + r.x, elu_fast(n1) + r.y);
            }
        }
        __syncthreads();
    }
}

// ---------------- gate: static tiles + double-buffered cp.async prefetch (reads g_haux) ----------------
__global__ void __launch_bounds__(256) gate_kernel(const float* __restrict__ gw1,
                                                   const float* __restrict__ gb1,
                                                   const float* __restrict__ gw2,
                                                   const float* __restrict__ gb2) {
    __shared__ __half2 sW[64 * 72];
    __shared__ __half2 sA[2][128 * 68];
    __shared__ float sb1[64], sw2[64];
    __shared__ float sb2s;
    int tid = threadIdx.x, lane = tid & 31, warp = tid >> 5;
    int tg = lane & 3, g = lane >> 2;
    for (int i = tid; i < 64 * 64; i += 256) {
        int kp = i >> 6, n = i & 63;
        sW[kp * 72 + n] = __floats2half2_rn(gw1[(2 * kp) * 64 + n], gw1[(2 * kp + 1) * 64 + n]);
    }
    if (tid < 64) { sb1[tid] = gb1[tid]; sw2[tid] = gw2[tid]; }
    if (tid == 0) sb2s = gb2[0];

    auto stage = [&](int tile, int buf) {
        int rowbase = tile * 128;
        __half2* dst = sA[buf];
        for (int f = tid; f < 4096; f += 256) {
            int r = f >> 5, j = f & 31;
            int grow = rowbase + r;
            bool ok = grow < N_NODES;
            int growc = ok ? grow : (N_NODES - 1);
            const void* src = (const void*)(((const uint2*)(g_haux + (size_t)growc * 64)) + j);
            cp8(&dst[r * 68 + j * 2], src, ok);
        }
        CP_COMMIT();
    };

    int tile = blockIdx.x;
    int buf = 0;
    if (tile < NTILES) stage(tile, 0);
    __syncthreads();

    for (; tile < NTILES; tile += gridDim.x) {
        CP_WAIT0();
        __syncthreads();
        int nt = tile + gridDim.x;
        if (nt < NTILES) stage(nt, buf ^ 1);

        float acc[8][4];
#pragma unroll
        for (int t = 0; t < 8; t++) { acc[t][0]=0.f; acc[t][1]=0.f; acc[t][2]=0.f; acc[t][3]=0.f; }

        const __half2* a0p = &sA[buf][(warp * 16 + g) * 68];
        const __half2* a1p = a0p + 8 * 68;
#pragma unroll
        for (int s = 0; s < 8; s++) {
            int kpo = s * 8;
            unsigned A0 = h2u(a0p[kpo + tg]);
            unsigned A1 = h2u(a1p[kpo + tg]);
            unsigned A2 = h2u(a0p[kpo + tg + 4]);
            unsigned A3 = h2u(a1p[kpo + tg + 4]);
            const __half2* bb  = &sW[(kpo + tg) * 72 + g];
            const __half2* bb2 = bb + 4 * 72;
#pragma unroll
            for (int t = 0; t < 8; t++)
                mma_f16(acc[t][0], acc[t][1], acc[t][2], acc[t][3],
                        A0, A1, A2, A3, h2u(bb[t * 8]), h2u(bb2[t * 8]));
        }
        int rowbase = tile * 128;
        int grow0 = rowbase + warp * 16 + g;
        int grow1 = grow0 + 8;
        float rr0 = 0.f, rr1 = 0.f;
#pragma unroll
        for (int t = 0; t < 8; t++) {
            int c = t * 8 + tg * 2;
            rr0 += fmaxf(acc[t][0] + sb1[c], 0.f) * sw2[c]
                 + fmaxf(acc[t][1] + sb1[c + 1], 0.f) * sw2[c + 1];
            rr1 += fmaxf(acc[t][2] + sb1[c], 0.f) * sw2[c]
                 + fmaxf(acc[t][3] + sb1[c + 1], 0.f) * sw2[c + 1];
        }
#pragma unroll
        for (int o = 1; o <= 2; o <<= 1) {
            rr0 += __shfl_xor_sync(0xffffffffu, rr0, o);
            rr1 += __shfl_xor_sync(0xffffffffu, rr1, o);
        }
        if (tg == 0) {
            if (grow0 < N_NODES) g_gate[grow0] = rr0 + sb2s;
            if (grow1 < N_NODES) g_gate[grow1] = rr1 + sb2s;
        }
        buf ^= 1;
        __syncthreads();
    }
}

// ---------------- fused graph pooling + classifier (reads g_haux) ----------------
__global__ void __launch_bounds__(256) graphpool_kernel(const int* __restrict__ batch,
                                                        const float* __restrict__ w1,
                                                        const float* __restrict__ b1,
                                                        const float* __restrict__ w2,
                                                        const float* __restrict__ b2,
                                                        float* __restrict__ out) {
    int gidx = blockIdx.x;
    int tid = threadIdx.x, lane = tid & 31, warp = tid >> 5;
    __shared__ float red[8];
    __shared__ float sp[8][HDIM];
    __shared__ float pooled[HDIM];
    __shared__ float hid[64];

    auto lower_bound = [&](int val) {
        int lo = 0, hi = N_NODES;
        while (lo < hi) { int mid = (lo + hi) >> 1; if (batch[mid] < val) lo = mid + 1; else hi = mid; }
        return lo;
    };
    int start = lower_bound(gidx);
    int end   = lower_bound(gidx + 1);

    float m = -3.0e38f;
    for (int i = start + tid; i < end; i += 256) m = fmaxf(m, g_gate[i]);
#pragma unroll
    for (int o = 16; o; o >>= 1) m = fmaxf(m, __shfl_xor_sync(0xffffffffu, m, o));
    if (lane == 0) red[warp] = m;
    __syncthreads();
    float gm = red[0];
#pragma unroll
    for (int wj = 1; wj < 8; wj++) gm = fmaxf(gm, red[wj]);
    __syncthreads();

    float s = 0.f;
    for (int i = start + tid; i < end; i += 256) s += __expf(g_gate[i] - gm);
#pragma unroll
    for (int o = 16; o; o >>= 1) s += __shfl_xor_sync(0xffffffffu, s, o);
    if (lane == 0) red[warp] = s;
    __syncthreads();
    float denom = red[0] + red[1] + red[2] + red[3] + red[4] + red[5] + red[6] + red[7];
    float invd = (denom > 0.f) ? (1.0f / denom) : 0.f;

    float a0 = 0.f, a1 = 0.f, a2 = 0.f, a3 = 0.f;
    const uint2* hb = reinterpret_cast<const uint2*>(g_haux);
    for (int row = start + warp; row < end; row += 8) {
        float e = __expf(g_gate[row] - gm);
        uint2 u = hb[(size_t)row * 32 + lane];
        float2 p = __half22float2(u2h(u.x));
        float2 q = __half22float2(u2h(u.y));
        a0 += e * p.x; a1 += e * p.y; a2 += e * q.x; a3 += e * q.y;
    }
    sp[warp][lane * 4]     = a0;
    sp[warp][lane * 4 + 1] = a1;
    sp[warp][lane * 4 + 2] = a2;
    sp[warp][lane * 4 + 3] = a3;
    __syncthreads();
    if (tid < HDIM) {
        float p = 0.f;
#pragma unroll
        for (int wj = 0; wj < 8; wj++) p += sp[wj][tid];
        pooled[tid] = p * invd;
    }
    __syncthreads();

    if (tid < 64) {
        float acc = b1[tid];
#pragma unroll
        for (int k = 0; k < HDIM; k++) acc += pooled[k] * w1[k * 64 + tid];
        hid[tid] = fmaxf(acc, 0.f);
    }
    __syncthreads();
    if (tid < NCLASSES) {
        float o = b2[tid];
#pragma unroll
        for (int k = 0; k < 64; k++) o += hid[k] * w2[k * NCLASSES + tid];
        out[(size_t)gidx * NCLASSES + tid] = o;
    }
}

// ---------------- launch ----------------
extern "C" void kernel_launch(void* const* d_in, const int* in_sizes, int n_in,
                              void* d_out, int out_size) {
    const float* x       = (const float*)d_in[0];
    const int*   ei      = (const int*)d_in[1];
    const int*   batch   = (const int*)d_in[2];
    const float* proj_w  = (const float*)d_in[3];
    const float* proj_b  = (const float*)d_in[4];
    const float* lin_l_w = (const float*)d_in[5];
    const float* lin_l_b = (const float*)d_in[6];
    const float* lin_r_w = (const float*)d_in[7];
    const float* ln_g    = (const float*)d_in[8];
    const float* ln_b    = (const float*)d_in[9];
    const float* gate_w1 = (const float*)d_in[10];
    const float* gate_b1 = (const float*)d_in[11];
    const float* gate_w2 = (const float*)d_in[12];
    const float* gate_b2 = (const float*)d_in[13];
    const float* cls_w1  = (const float*)d_in[14];
    const float* cls_b1  = (const float*)d_in[15];
    const float* cls_w2  = (const float*)d_in[16];
    const float* cls_b2  = (const float*)d_in[17];
    float* out = (float*)d_out;

    static bool attr_set = false;
    static cudaStream_t s2 = nullptr;
    static cudaEvent_t ev_fork = nullptr, ev_join = nullptr;
    if (!attr_set) {
        cudaFuncSetAttribute(layer_kernel, cudaFuncAttributeMaxDynamicSharedMemorySize, LAYER_SMEM);
        cudaStreamCreateWithFlags(&s2, cudaStreamNonBlocking);
        cudaEventCreateWithFlags(&ev_fork, cudaEventDisableTiming);
        cudaEventCreateWithFlags(&ev_join, cudaEventDisableTiming);
        attr_set = true;
    }

    init_kernel<<<512, 256>>>();
    cudaEventRecord(ev_fork, 0);
    cudaStreamWaitEvent(s2, ev_fork, 0);
    proj_kernel<<<296, 256, 0, s2>>>(x, proj_w, proj_b);
    cudaEventRecord(ev_join, s2);

    deg_kernel<<<2048, 256>>>(ei);
    scan_a_kernel<<<NBLK, 1024>>>();
    scan_b_kernel<<<1, 128>>>();
    scan_c_kernel<<<NBLK, 1024>>>();
    fill_kernel<<<2048, 256>>>(ei);
    cudaStreamWaitEvent(0, ev_join, 0);

    for (int l = 0; l < NLAYERS; l++) {
        layer_kernel<<<296, 256, LAYER_SMEM>>>(lin_l_w + (size_t)l * HDIM * HDIM,
                                               lin_l_b + (size_t)l * HDIM,
                                               lin_r_w + (size_t)l * HDIM * HDIM,
                                               ln_g + (size_t)l * HDIM,
                                               ln_b + (size_t)l * HDIM,
                                               l);
    }

    gate_kernel<<<296, 256>>>(gate_w1, gate_b1, gate_w2, gate_b2);
    graphpool_kernel<<<NGRAPHS, 256>>>(batch, cls_w1, cls_b1, cls_w2, cls_b2, out);
}

// round 17
// speedup vs baseline: 1.2545x; 1.2545x over previous
#include <cuda_runtime.h>
#include <cuda_fp16.h>
#include <cstdint>

#define N_NODES   100000
#define NUM_E     1600000
#define DIM_IN    64
#define HDIM      128
#define NLAYERS   3
#define NGRAPHS   512
#define NCLASSES  6
#define LN_EPS    1e-5f
#define NBLK      98
#define NTILES    782          // ceil(100000/128)
#define CNT_PROJ  NLAYERS
#define NCNT      (NLAYERS + 1)

// layer smem (half2 units): weights + 2 staging buffers of 32 kp
#define SWH_STRIDE 136
#define SWH_ELEMS  (128 * SWH_STRIDE)
#define SAH_STRIDE 36
#define SAH_BUF    (128 * SAH_STRIDE)
#define LAYER_SMEM ((SWH_ELEMS + 2 * SAH_BUF) * 4)

// ---------------- scratch ----------------
__device__ __half2 g_hf[(size_t)N_NODES * HDIM / 2];     // THE node features (fp16)
__device__ __half2 g_aggr2[(size_t)N_NODES * HDIM / 2];  // fp16 mean-aggregated
__device__ float   g_invdeg[N_NODES];
__device__ int     g_deg[N_NODES];
__device__ int     g_off[N_NODES + 1];
__device__ int     g_cursor[N_NODES];
__device__ int     g_csr[NUM_E];
__device__ int     g_bsum[NBLK];
__device__ int     g_boff[NBLK];
__device__ int     g_cnt[NCNT];
__device__ float   g_gate[N_NODES];

// ---------------- helpers ----------------
__device__ __forceinline__ void mma_f16(float& d0, float& d1, float& d2, float& d3,
                                        unsigned a0, unsigned a1, unsigned a2, unsigned a3,
                                        unsigned b0, unsigned b1) {
    asm volatile("mma.sync.aligned.m16n8k16.row.col.f32.f16.f16.f32 "
                 "{%0,%1,%2,%3},{%4,%5,%6,%7},{%8,%9},{%0,%1,%2,%3};"
                 : "+f"(d0), "+f"(d1), "+f"(d2), "+f"(d3)
                 : "r"(a0), "r"(a1), "r"(a2), "r"(a3), "r"(b0), "r"(b1));
}
__device__ __forceinline__ unsigned h2u(__half2 h) { return *(unsigned*)&h; }
__device__ __forceinline__ __half2 u2h(unsigned u) { return *(__half2*)&u; }
__device__ __forceinline__ float elu_fast(float n) {
    return n > 0.f ? n : (__expf(n) - 1.0f);
}
__device__ __forceinline__ void cp16(void* smem_dst, const void* gsrc, bool pred) {
    unsigned sa = (unsigned)__cvta_generic_to_shared(smem_dst);
    int sz = pred ? 16 : 0;
    asm volatile("cp.async.cg.shared.global [%0], [%1], 16, %2;" :: "r"(sa), "l"(gsrc), "r"(sz));
}
#define CP_COMMIT() asm volatile("cp.async.commit_group;")
#define CP_WAIT0()  asm volatile("cp.async.wait_group 0;")

// ---------------- init / degree / CSR ----------------
__global__ void init_kernel() {
    int i = blockIdx.x * blockDim.x + threadIdx.x;
    int stride = gridDim.x * blockDim.x;
    for (int idx = i; idx < N_NODES; idx += stride) g_deg[idx] = 0;
    if (i < NCNT) g_cnt[i] = 0;
}
__global__ void deg_kernel(const int* __restrict__ ei) {
    int i = blockIdx.x * blockDim.x + threadIdx.x;
    int stride = gridDim.x * blockDim.x;
    for (int e = i; e < NUM_E; e += stride) atomicAdd(&g_deg[ei[NUM_E + e]], 1);
}
__global__ void __launch_bounds__(1024) scan_a_kernel() {
    int i = blockIdx.x * 1024 + threadIdx.x;
    int lane = threadIdx.x & 31;
    int v = (i < N_NODES) ? g_deg[i] : 0;
#pragma unroll
    for (int o = 16; o; o >>= 1) v += __shfl_xor_sync(0xffffffffu, v, o);
    __shared__ int wsum[32];
    if (lane == 0) wsum[threadIdx.x >> 5] = v;
    __syncthreads();
    if (threadIdx.x < 32) {
        int t = wsum[threadIdx.x];
#pragma unroll
        for (int o = 16; o; o >>= 1) t += __shfl_xor_sync(0xffffffffu, t, o);
        if (threadIdx.x == 0) g_bsum[blockIdx.x] = t;
    }
}
__global__ void __launch_bounds__(128) scan_b_kernel() {
    __shared__ int sm[128];
    int t = threadIdx.x;
    int v = (t < NBLK) ? g_bsum[t] : 0;
    sm[t] = v; __syncthreads();
    for (int o = 1; o < 128; o <<= 1) {
        int tmp = (t >= o) ? sm[t - o] : 0;
        __syncthreads();
        sm[t] += tmp;
        __syncthreads();
    }
    if (t < NBLK) g_boff[t] = sm[t] - v;
    if (t == NBLK - 1) g_off[N_NODES] = sm[t];
}
__global__ void __launch_bounds__(1024) scan_c_kernel() {
    __shared__ int sm[1024];
    int t = threadIdx.x;
    int i = blockIdx.x * 1024 + t;
    int v = (i < N_NODES) ? g_deg[i] : 0;
    sm[t] = v; __syncthreads();
    for (int o = 1; o < 1024; o <<= 1) {
        int tmp = (t >= o) ? sm[t - o] : 0;
        __syncthreads();
        sm[t] += tmp;
        __syncthreads();
    }
    if (i < N_NODES) {
        int off = g_boff[blockIdx.x] + sm[t] - v;
        g_off[i] = off;
        g_cursor[i] = off;
        g_invdeg[i] = 1.0f / fmaxf((float)v, 1.0f);
    }
}
__global__ void fill_kernel(const int* __restrict__ ei) {
    int i = blockIdx.x * blockDim.x + threadIdx.x;
    int stride = gridDim.x * blockDim.x;
    for (int e = i; e < NUM_E; e += stride) {
        int src = ei[e];
        int dst = ei[NUM_E + e];
        int p = atomicAdd(&g_cursor[dst], 1);
        g_csr[p] = src;
    }
}

// ---------------- aggregation: half-warp LDG.128 gather, HADD2 tree ----------------
__global__ void __launch_bounds__(256) aggregate_kernel() {
    int tid = blockIdx.x * blockDim.x + threadIdx.x;
    int gw = tid >> 5;
    int lane = threadIdx.x & 31;
    int half = lane >> 4, lh = lane & 15;
    int nw = (gridDim.x * blockDim.x) >> 5;
    const uint4* hb = reinterpret_cast<const uint4*>(g_hf);
#define FOLD(U) { float2 f; \
    f = __half22float2(u2h((U).x)); a0 += f.x; a1 += f.y; \
    f = __half22float2(u2h((U).y)); a2 += f.x; a3 += f.y; \
    f = __half22float2(u2h((U).z)); a4 += f.x; a5 += f.y; \
    f = __half22float2(u2h((U).w)); a6 += f.x; a7 += f.y; }
    for (int v = gw; v < N_NODES; v += nw) {
        int beg = g_off[v], end = g_off[v + 1];
        int cnt = end - beg;
        float a0=0.f,a1=0.f,a2=0.f,a3=0.f,a4=0.f,a5=0.f,a6=0.f,a7=0.f;
        int e16 = beg + (cnt & ~15);
        int e = beg + half;
        for (; e < e16; e += 16) {
            int i0 = g_csr[e],      i1 = g_csr[e + 2];
            int i2 = g_csr[e + 4],  i3 = g_csr[e + 6];
            int i4 = g_csr[e + 8],  i5 = g_csr[e + 10];
            int i6 = g_csr[e + 12], i7 = g_csr[e + 14];
            uint4 u0 = hb[(size_t)i0 * 16 + lh];
            uint4 u1 = hb[(size_t)i1 * 16 + lh];
            uint4 u2 = hb[(size_t)i2 * 16 + lh];
            uint4 u3 = hb[(size_t)i3 * 16 + lh];
            uint4 u4 = hb[(size_t)i4 * 16 + lh];
            uint4 u5 = hb[(size_t)i5 * 16 + lh];
            uint4 u6 = hb[(size_t)i6 * 16 + lh];
            uint4 u7 = hb[(size_t)i7 * 16 + lh];
            uint4 s;
            s.x = h2u(__hadd2(__hadd2(__hadd2(u2h(u0.x), u2h(u1.x)), __hadd2(u2h(u2.x), u2h(u3.x))),
                              __hadd2(__hadd2(u2h(u4.x), u2h(u5.x)), __hadd2(u2h(u6.x), u2h(u7.x)))));
            s.y = h2u(__hadd2(__hadd2(__hadd2(u2h(u0.y), u2h(u1.y)), __hadd2(u2h(u2.y), u2h(u3.y))),
                              __hadd2(__hadd2(u2h(u4.y), u2h(u5.y)), __hadd2(u2h(u6.y), u2h(u7.y)))));
            s.z = h2u(__hadd2(__hadd2(__hadd2(u2h(u0.z), u2h(u1.z)), __hadd2(u2h(u2.z), u2h(u3.z))),
                              __hadd2(__hadd2(u2h(u4.z), u2h(u5.z)), __hadd2(u2h(u6.z), u2h(u7.z)))));
            s.w = h2u(__hadd2(__hadd2(__hadd2(u2h(u0.w), u2h(u1.w)), __hadd2(u2h(u2.w), u2h(u3.w))),
                              __hadd2(__hadd2(u2h(u4.w), u2h(u5.w)), __hadd2(u2h(u6.w), u2h(u7.w)))));
            FOLD(s)
        }
        int end_even = end - (cnt & 1);
        for (; e < end_even; e += 2) {
            uint4 u = hb[(size_t)g_csr[e] * 16 + lh];
            FOLD(u)
        }
        if ((cnt & 1) && half == 0) {
            uint4 u = hb[(size_t)g_csr[end - 1] * 16 + lh];
            FOLD(u)
        }
        a0 += __shfl_xor_sync(0xffffffffu, a0, 16);
        a1 += __shfl_xor_sync(0xffffffffu, a1, 16);
        a2 += __shfl_xor_sync(0xffffffffu, a2, 16);
        a3 += __shfl_xor_sync(0xffffffffu, a3, 16);
        a4 += __shfl_xor_sync(0xffffffffu, a4, 16);
        a5 += __shfl_xor_sync(0xffffffffu, a5, 16);
        a6 += __shfl_xor_sync(0xffffffffu, a6, 16);
        a7 += __shfl_xor_sync(0xffffffffu, a7, 16);
        if (half == 0) {
            float inv = g_invdeg[v];
            uint4 o;
            o.x = h2u(__floats2half2_rn(a0 * inv, a1 * inv));
            o.y = h2u(__floats2half2_rn(a2 * inv, a3 * inv));
            o.z = h2u(__floats2half2_rn(a4 * inv, a5 * inv));
            o.w = h2u(__floats2half2_rn(a6 * inv, a7 * inv));
            ((uint4*)g_aggr2)[(size_t)v * 16 + lh] = o;
        }
    }
#undef FOLD
}

// ---------------- projection (fp16 mma, staged A): h = relu(x @ W + b) ----------------
__global__ void __launch_bounds__(256) proj_kernel(const float* __restrict__ x,
                                                   const float* __restrict__ w,
                                                   const float* __restrict__ b) {
    __shared__ __half2 sW[32 * 136];
    __shared__ __half2 sX[128 * 36];
    __shared__ float sbias[128];
    __shared__ int s_tile;
    int tid = threadIdx.x, lane = tid & 31, warp = tid >> 5;
    int tg = lane & 3, g = lane >> 2;
    for (int i = tid; i < 32 * 128; i += 256) {
        int kp = i >> 7, n = i & 127;
        sW[kp * 136 + n] = __floats2half2_rn(w[(2 * kp) * HDIM + n], w[(2 * kp + 1) * HDIM + n]);
    }
    if (tid < 128) sbias[tid] = b[tid];
    __syncthreads();

    while (true) {
        if (tid == 0) s_tile = atomicAdd(&g_cnt[CNT_PROJ], 1);
        __syncthreads();
        int tile = s_tile;
        if (tile >= NTILES) break;
        int rowbase = tile * 128;

        for (int f = tid; f < 2048; f += 256) {
            int r = f >> 4, q = f & 15;
            int grow = rowbase + r;
            float4 v = make_float4(0.f, 0.f, 0.f, 0.f);
            if (grow < N_NODES) v = ((const float4*)(x + (size_t)grow * DIM_IN))[q];
            sX[r * 36 + q * 2]     = __floats2half2_rn(v.x, v.y);
            sX[r * 36 + q * 2 + 1] = __floats2half2_rn(v.z, v.w);
        }
        __syncthreads();

        float acc[16][4];
#pragma unroll
        for (int t = 0; t < 16; t++) { acc[t][0]=0.f; acc[t][1]=0.f; acc[t][2]=0.f; acc[t][3]=0.f; }

        const __half2* a0p = &sX[(warp * 16 + g) * 36];
        const __half2* a1p = a0p + 8 * 36;
#pragma unroll
        for (int s = 0; s < 4; s++) {
            int kpo = s * 8;
            unsigned A0 = h2u(a0p[kpo + tg]);
            unsigned A1 = h2u(a1p[kpo + tg]);
            unsigned A2 = h2u(a0p[kpo + tg + 4]);
            unsigned A3 = h2u(a1p[kpo + tg + 4]);
            const __half2* bb  = &sW[(kpo + tg) * 136 + g];
            const __half2* bb2 = bb + 4 * 136;
#pragma unroll
            for (int t = 0; t < 16; t++)
                mma_f16(acc[t][0], acc[t][1], acc[t][2], acc[t][3],
                        A0, A1, A2, A3, h2u(bb[t * 8]), h2u(bb2[t * 8]));
        }

        int grow0 = rowbase + warp * 16 + g;
        int grow1 = grow0 + 8;
        if (grow0 < N_NODES) {
#pragma unroll
            for (int t = 0; t < 16; t++) {
                int c = t * 8 + tg * 2;
                g_hf[((size_t)grow0 * HDIM + c) >> 1] =
                    __floats2half2_rn(fmaxf(acc[t][0] + sbias[c], 0.f),
                                      fmaxf(acc[t][1] + sbias[c + 1], 0.f));
            }
        }
        if (grow1 < N_NODES) {
#pragma unroll
            for (int t = 0; t < 16; t++) {
                int c = t * 8 + tg * 2;
                g_hf[((size_t)grow1 * HDIM + c) >> 1] =
                    __floats2half2_rn(fmaxf(acc[t][2] + sbias[c], 0.f),
                                      fmaxf(acc[t][3] + sbias[c + 1], 0.f));
            }
        }
        __syncthreads();
    }
}

// ---------------- fused layer: fp16 mma K=256, 4 staging chunks of 32 kp ----------------
__global__ void __launch_bounds__(256, 2) layer_kernel(const float* __restrict__ wl,
                                                       const float* __restrict__ bl,
                                                       const float* __restrict__ wr,
                                                       const float* __restrict__ lg,
                                                       const float* __restrict__ lb,
                                                       int lidx) {
    extern __shared__ __half2 smh[];
    __half2* sW = smh;
    __half2* sA = smh + SWH_ELEMS;
    __shared__ float sGB[384];
    __shared__ int s_tile;
    int tid = threadIdx.x, lane = tid & 31, warp = tid >> 5;
    int tg = lane & 3, g = lane >> 2;
    if (tid < 128) { sGB[tid] = lg[tid]; sGB[128 + tid] = lb[tid]; sGB[256 + tid] = bl[tid]; }
    for (int i = tid; i < 128 * 128; i += 256) {
        int kp = i >> 7, n = i & 127;
        float w0, w1;
        if (kp < 64) { w0 = wl[(2 * kp) * HDIM + n];       w1 = wl[(2 * kp + 1) * HDIM + n]; }
        else { int r = 2 * kp - 128; w0 = wr[r * HDIM + n]; w1 = wr[(r + 1) * HDIM + n]; }
        sW[kp * SWH_STRIDE + n] = __floats2half2_rn(w0, w1);
    }
    __syncthreads();

    while (true) {
        if (tid == 0) s_tile = atomicAdd(&g_cnt[lidx], 1);
        __syncthreads();
        int tile = s_tile;
        if (tile >= NTILES) break;
        int rowbase = tile * 128;

        // chunk = 32 kp: ch 0-1 from aggr2 (kp 0..63), ch 2-3 from hf
        auto stage = [&](int ch) {
            __half2* dst = sA + (ch & 1) * SAH_BUF;
            const __half2* base = (ch < 2) ? g_aggr2 : g_hf;
            int kpb = (ch < 2) ? ch * 32 : (ch - 2) * 32;
            for (int f = tid; f < 1024; f += 256) {   // 128 rows x 8 uint4
                int r = f >> 3, j = f & 7;
                int grow = rowbase + r;
                bool ok = grow < N_NODES;
                int growc = ok ? grow : (N_NODES - 1);
                const void* src = (const void*)((const uint4*)(base + (size_t)growc * 64 + kpb) + j);
                cp16(&dst[r * SAH_STRIDE + j * 4], src, ok);
            }
            CP_COMMIT();
        };

        float acc[16][4];
#pragma unroll
        for (int t = 0; t < 16; t++) { acc[t][0]=0.f; acc[t][1]=0.f; acc[t][2]=0.f; acc[t][3]=0.f; }

        stage(0);
        CP_WAIT0();
        __syncthreads();
#pragma unroll
        for (int ch = 0; ch < 4; ch++) {
            __half2* cur = sA + (ch & 1) * SAH_BUF;
            if (ch < 3) stage(ch + 1);              // overlaps mma below
            const __half2* a0p = &cur[(warp * 16 + g) * SAH_STRIDE];
            const __half2* a1p = a0p + 8 * SAH_STRIDE;
#pragma unroll
            for (int s2 = 0; s2 < 4; s2++) {
                int kpo = s2 * 8;
                unsigned A0 = h2u(a0p[kpo + tg]);
                unsigned A1 = h2u(a1p[kpo + tg]);
                unsigned A2 = h2u(a0p[kpo + tg + 4]);
                unsigned A3 = h2u(a1p[kpo + tg + 4]);
                const __half2* bb  = &sW[(ch * 32 + kpo + tg) * SWH_STRIDE + g];
                const __half2* bb2 = bb + 4 * SWH_STRIDE;
#pragma unroll
                for (int t = 0; t < 16; t++)
                    mma_f16(acc[t][0], acc[t][1], acc[t][2], acc[t][3],
                            A0, A1, A2, A3, h2u(bb[t * 8]), h2u(bb2[t * 8]));
            }
            if (ch < 3) CP_WAIT0();
            __syncthreads();
        }

        int grow0 = rowbase + warp * 16 + g;
        int grow1 = grow0 + 8;
        bool v0 = grow0 < N_NODES, v1 = grow1 < N_NODES;
        float s0 = 0.f, q0 = 0.f, s1 = 0.f, q1 = 0.f;
#pragma unroll
        for (int t = 0; t < 16; t++) {
            int c = t * 8 + tg * 2;
            float bb0 = sGB[256 + c], bb1 = sGB[256 + c + 1];
            acc[t][0] += bb0; acc[t][1] += bb1; acc[t][2] += bb0; acc[t][3] += bb1;
            s0 += acc[t][0] + acc[t][1]; q0 += acc[t][0]*acc[t][0] + acc[t][1]*acc[t][1];
            s1 += acc[t][2] + acc[t][3]; q1 += acc[t][2]*acc[t][2] + acc[t][3]*acc[t][3];
        }
#pragma unroll
        for (int o = 1; o <= 2; o <<= 1) {
            s0 += __shfl_xor_sync(0xffffffffu, s0, o);
            q0 += __shfl_xor_sync(0xffffffffu, q0, o);
            s1 += __shfl_xor_sync(0xffffffffu, s1, o);
            q1 += __shfl_xor_sync(0xffffffffu, q1, o);
        }
        float mu0 = s0 * (1.0f / HDIM), mu1 = s1 * (1.0f / HDIM);
        float rs0 = rsqrtf(q0 * (1.0f / HDIM) - mu0 * mu0 + LN_EPS);
        float rs1 = rsqrtf(q1 * (1.0f / HDIM) - mu1 * mu1 + LN_EPS);
        if (v0) {
#pragma unroll
            for (int t = 0; t < 16; t++) {
                int c = t * 8 + tg * 2;
                float n0 = (acc[t][0] - mu0) * rs0 * sGB[c] + sGB[128 + c];
                float n1 = (acc[t][1] - mu0) * rs0 * sGB[c + 1] + sGB[128 + c + 1];
                size_t hi = ((size_t)grow0 * HDIM + c) >> 1;
                float2 r = __half22float2(g_hf[hi]);
                g_hf[hi] = __floats2half2_rn(elu_fast(n0) + r.x, elu_fast(n1) + r.y);
            }
        }
        if (v1) {
#pragma unroll
            for (int t = 0; t < 16; t++) {
                int c = t * 8 + tg * 2;
                float n0 = (acc[t][2] - mu1) * rs1 * sGB[c] + sGB[128 + c];
                float n1 = (acc[t][3] - mu1) * rs1 * sGB[c + 1] + sGB[128 + c + 1];
                size_t hi = ((size_t)grow1 * HDIM + c) >> 1;
                float2 r = __half22float2(g_hf[hi]);
                g_hf[hi] = __floats2half2_rn(elu_fast(n0) + r.x, elu_fast(n1) + r.y);
            }
        }
        __syncthreads();
    }
}

// ---------------- gate: static tiles + double-buffered cp.async prefetch ----------------
__global__ void __launch_bounds__(256) gate_kernel(const float* __restrict__ gw1,
                                                   const float* __restrict__ gb1,
                                                   const float* __restrict__ gw2,
                                                   const float* __restrict__ gb2) {
    __shared__ __half2 sW[64 * 72];
    __shared__ __half2 sA[2][128 * 68];
    __shared__ float sb1[64], sw2[64];
    __shared__ float sb2s;
    int tid = threadIdx.x, lane = tid & 31, warp = tid >> 5;
    int tg = lane & 3, g = lane >> 2;
    for (int i = tid; i < 64 * 64; i += 256) {
        int kp = i >> 6, n = i & 63;
        sW[kp * 72 + n] = __floats2half2_rn(gw1[(2 * kp) * 64 + n], gw1[(2 * kp + 1) * 64 + n]);
    }
    if (tid < 64) { sb1[tid] = gb1[tid]; sw2[tid] = gw2[tid]; }
    if (tid == 0) sb2s = gb2[0];

    auto stage = [&](int tile, int buf) {
        int rowbase = tile * 128;
        __half2* dst = sA[buf];
        for (int f = tid; f < 2048; f += 256) {   // 128 rows x 16 uint4
            int r = f >> 4, j = f & 15;
            int grow = rowbase + r;
            bool ok = grow < N_NODES;
            int growc = ok ? grow : (N_NODES - 1);
            const void* src = (const void*)(((const uint4*)(g_hf + (size_t)growc * 64)) + j);
            cp16(&dst[r * 68 + j * 4], src, ok);
        }
        CP_COMMIT();
    };

    int tile = blockIdx.x;
    int buf = 0;
    if (tile < NTILES) stage(tile, 0);
    __syncthreads();

    for (; tile < NTILES; tile += gridDim.x) {
        CP_WAIT0();
        __syncthreads();
        int nt = tile + gridDim.x;
        if (nt < NTILES) stage(nt, buf ^ 1);   // prefetch next tile during mma

        float acc[8][4];
#pragma unroll
        for (int t = 0; t < 8; t++) { acc[t][0]=0.f; acc[t][1]=0.f; acc[t][2]=0.f; acc[t][3]=0.f; }

        const __half2* a0p = &sA[buf][(warp * 16 + g) * 68];
        const __half2* a1p = a0p + 8 * 68;
#pragma unroll
        for (int s = 0; s < 8; s++) {
            int kpo = s * 8;
            unsigned A0 = h2u(a0p[kpo + tg]);
            unsigned A1 = h2u(a1p[kpo + tg]);
            unsigned A2 = h2u(a0p[kpo + tg + 4]);
            unsigned A3 = h2u(a1p[kpo + tg + 4]);
            const __half2* bb  = &sW[(kpo + tg) * 72 + g];
            const __half2* bb2 = bb + 4 * 72;
#pragma unroll
            for (int t = 0; t < 8; t++)
                mma_f16(acc[t][0], acc[t][1], acc[t][2], acc[t][3],
                        A0, A1, A2, A3, h2u(bb[t * 8]), h2u(bb2[t * 8]));
        }
        int rowbase = tile * 128;
        int grow0 = rowbase + warp * 16 + g;
        int grow1 = grow0 + 8;
        float rr0 = 0.f, rr1 = 0.f;
#pragma unroll
        for (int t = 0; t < 8; t++) {
            int c = t * 8 + tg * 2;
            rr0 += fmaxf(acc[t][0] + sb1[c], 0.f) * sw2[c]
                 + fmaxf(acc[t][1] + sb1[c + 1], 0.f) * sw2[c + 1];
            rr1 += fmaxf(acc[t][2] + sb1[c], 0.f) * sw2[c]
                 + fmaxf(acc[t][3] + sb1[c + 1], 0.f) * sw2[c + 1];
        }
#pragma unroll
        for (int o = 1; o <= 2; o <<= 1) {
            rr0 += __shfl_xor_sync(0xffffffffu, rr0, o);
            rr1 += __shfl_xor_sync(0xffffffffu, rr1, o);
        }
        if (tg == 0) {
            if (grow0 < N_NODES) g_gate[grow0] = rr0 + sb2s;
            if (grow1 < N_NODES) g_gate[grow1] = rr1 + sb2s;
        }
        buf ^= 1;
        __syncthreads();
    }
}

// ---------------- fused graph pooling + classifier: one block per graph ----------------
__global__ void __launch_bounds__(256) graphpool_kernel(const int* __restrict__ batch,
                                                        const float* __restrict__ w1,
                                                        const float* __restrict__ b1,
                                                        const float* __restrict__ w2,
                                                        const float* __restrict__ b2,
                                                        float* __restrict__ out) {
    int gidx = blockIdx.x;
    int tid = threadIdx.x, lane = tid & 31, warp = tid >> 5;
    __shared__ float red[8];
    __shared__ float sp[8][HDIM];
    __shared__ float pooled[HDIM];
    __shared__ float hid[64];

    auto lower_bound = [&](int val) {
        int lo = 0, hi = N_NODES;
        while (lo < hi) { int mid = (lo + hi) >> 1; if (batch[mid] < val) lo = mid + 1; else hi = mid; }
        return lo;
    };
    int start = lower_bound(gidx);
    int end   = lower_bound(gidx + 1);

    float m = -3.0e38f;
    for (int i = start + tid; i < end; i += 256) m = fmaxf(m, g_gate[i]);
#pragma unroll
    for (int o = 16; o; o >>= 1) m = fmaxf(m, __shfl_xor_sync(0xffffffffu, m, o));
    if (lane == 0) red[warp] = m;
    __syncthreads();
    float gm = red[0];
#pragma unroll
    for (int wj = 1; wj < 8; wj++) gm = fmaxf(gm, red[wj]);
    __syncthreads();

    float s = 0.f;
    for (int i = start + tid; i < end; i += 256) s += __expf(g_gate[i] - gm);
#pragma unroll
    for (int o = 16; o; o >>= 1) s += __shfl_xor_sync(0xffffffffu, s, o);
    if (lane == 0) red[warp] = s;
    __syncthreads();
    float denom = red[0] + red[1] + red[2] + red[3] + red[4] + red[5] + red[6] + red[7];
    float invd = (denom > 0.f) ? (1.0f / denom) : 0.f;

    float a0 = 0.f, a1 = 0.f, a2 = 0.f, a3 = 0.f;
    const uint2* hb = reinterpret_cast<const uint2*>(g_hf);
    for (int row = start + warp; row < end; row += 8) {
        float e = __expf(g_gate[row] - gm);
        uint2 u = hb[(size_t)row * 32 + lane];
        float2 p = __half22float2(u2h(u.x));
        float2 q = __half22float2(u2h(u.y));
        a0 += e * p.x; a1 += e * p.y; a2 += e * q.x; a3 += e * q.y;
    }
    sp[warp][lane * 4]     = a0;
    sp[warp][lane * 4 + 1] = a1;
    sp[warp][lane * 4 + 2] = a2;
    sp[warp][lane * 4 + 3] = a3;
    __syncthreads();
    if (tid < HDIM) {
        float p = 0.f;
#pragma unroll
        for (int wj = 0; wj < 8; wj++) p += sp[wj][tid];
        pooled[tid] = p * invd;
    }
    __syncthreads();

    if (tid < 64) {
        float acc = b1[tid];
#pragma unroll
        for (int k = 0; k < HDIM; k++) acc += pooled[k] * w1[k * 64 + tid];
        hid[tid] = fmaxf(acc, 0.f);
    }
    __syncthreads();
    if (tid < NCLASSES) {
        float o = b2[tid];
#pragma unroll
        for (int k = 0; k < 64; k++) o += hid[k] * w2[k * NCLASSES + tid];
        out[(size_t)gidx * NCLASSES + tid] = o;
    }
}

// ---------------- launch ----------------
extern "C" void kernel_launch(void* const* d_in, const int* in_sizes, int n_in,
                              void* d_out, int out_size) {
    const float* x       = (const float*)d_in[0];
    const int*   ei      = (const int*)d_in[1];
    const int*   batch   = (const int*)d_in[2];
    const float* proj_w  = (const float*)d_in[3];
    const float* proj_b  = (const float*)d_in[4];
    const float* lin_l_w = (const float*)d_in[5];
    const float* lin_l_b = (const float*)d_in[6];
    const float* lin_r_w = (const float*)d_in[7];
    const float* ln_g    = (const float*)d_in[8];
    const float* ln_b    = (const float*)d_in[9];
    const float* gate_w1 = (const float*)d_in[10];
    const float* gate_b1 = (const float*)d_in[11];
    const float* gate_w2 = (const float*)d_in[12];
    const float* gate_b2 = (const float*)d_in[13];
    const float* cls_w1  = (const float*)d_in[14];
    const float* cls_b1  = (const float*)d_in[15];
    const float* cls_w2  = (const float*)d_in[16];
    const float* cls_b2  = (const float*)d_in[17];
    float* out = (float*)d_out;

    static bool attr_set = false;
    static cudaStream_t s2 = nullptr;
    static cudaEvent_t ev_fork = nullptr, ev_join = nullptr;
    if (!attr_set) {
        cudaFuncSetAttribute(layer_kernel, cudaFuncAttributeMaxDynamicSharedMemorySize, LAYER_SMEM);
        cudaStreamCreateWithFlags(&s2, cudaStreamNonBlocking);
        cudaEventCreateWithFlags(&ev_fork, cudaEventDisableTiming);
        cudaEventCreateWithFlags(&ev_join, cudaEventDisableTiming);
        attr_set = true;
    }

    init_kernel<<<512, 256>>>();
    cudaEventRecord(ev_fork, 0);
    cudaStreamWaitEvent(s2, ev_fork, 0);
    proj_kernel<<<296, 256, 0, s2>>>(x, proj_w, proj_b);
    cudaEventRecord(ev_join, s2);

    deg_kernel<<<2048, 256>>>(ei);
    scan_a_kernel<<<NBLK, 1024>>>();
    scan_b_kernel<<<1, 128>>>();
    scan_c_kernel<<<NBLK, 1024>>>();
    fill_kernel<<<2048, 256>>>(ei);
    cudaStreamWaitEvent(0, ev_join, 0);

    for (int l = 0; l < NLAYERS; l++) {
        aggregate_kernel<<<2048, 256>>>();
        layer_kernel<<<296, 256, LAYER_SMEM>>>(lin_l_w + (size_t)l * HDIM * HDIM,
                                               lin_l_b + (size_t)l * HDIM,
                                               lin_r_w + (size_t)l * HDIM * HDIM,
                                               ln_g + (size_t)l * HDIM,
                                               ln_b + (size_t)l * HDIM,
                                               l);
    }

    gate_kernel<<<296, 256>>>(gate_w1, gate_b1, gate_w2, gate_b2);
    graphpool_kernel<<<NGRAPHS, 256>>>(batch, cls_w1, cls_b1, cls_w2, cls_b2, out);
}